// round 3
// baseline (speedup 1.0000x reference)
#include <cuda_runtime.h>
#include <cstdint>

#define BATCH 32768
#define IDIM  128
#define HDIM  256
#define ADIM  32
#define MT    128
#define NT    512
#define NBLK  (BATCH/MT)
#define NC    64

#define AST     36
#define ASM_SZ  (128*AST)
#define WSM_SZ  (192*AST)
#define BUF_SZ  (ASM_SZ+WSM_SZ)
#define WPS_OFF (2*BUF_SZ)
#define WVS_OFF (WPS_OFF + ADIM*HDIM)
#define BIAS_OFF (WVS_OFF + HDIM)
#define SMEM_FLOATS (BIAS_OFF + 4*HDIM)
#define SMEM_DYN (SMEM_FLOATS*4)

static __device__ __forceinline__ float tf32r(float x) {
    float r; asm("cvt.rna.tf32.f32 %0, %1;" : "=f"(r) : "f"(x)); return r;
}
static __device__ __forceinline__ void mma8(float c[4], const uint32_t a[4],
                                            const uint32_t b[2]) {
    asm volatile(
        "mma.sync.aligned.m16n8k8.row.col.f32.tf32.tf32.f32 "
        "{%0,%1,%2,%3},{%4,%5,%6,%7},{%8,%9},{%0,%1,%2,%3};"
        : "+f"(c[0]), "+f"(c[1]), "+f"(c[2]), "+f"(c[3])
        : "r"(a[0]), "r"(a[1]), "r"(a[2]), "r"(a[3]), "r"(b[0]), "r"(b[1]));
}
static __device__ __forceinline__ float sigf(float x) {
    return __fdividef(1.0f, 1.0f + __expf(-x));
}
static __device__ __forceinline__ float tanhff(float x) {
    float ax = fabsf(x), e = __expf(-2.0f * ax);
    return copysignf(__fdividef(1.0f - e, 1.0f + e), x);
}
static __device__ __forceinline__ float gru1(float rp, float zp, float ip,
                                             float hp, float hv) {
    float r = sigf(rp), z = sigf(zp);
    float n = tanhff(ip + r * hp);
    return n + z * (hv - n);
}
static __device__ __forceinline__ float4 cvt4(float4 v) {
    v.x = tf32r(v.x); v.y = tf32r(v.y); v.z = tf32r(v.z); v.w = tf32r(v.w);
    return v;
}

__global__ void __launch_bounds__(NT, 1)
gru_ac_kernel(const float* __restrict__ x,    const float* __restrict__ hin,
              const float* __restrict__ wih0, const float* __restrict__ whh0,
              const float* __restrict__ bih0, const float* __restrict__ bhh0,
              const float* __restrict__ wih1, const float* __restrict__ whh1,
              const float* __restrict__ bih1, const float* __restrict__ bhh1,
              const float* __restrict__ wp,   const float* __restrict__ bp,
              const float* __restrict__ wv,   const float* __restrict__ bv,
              float* __restrict__ out)
{
    extern __shared__ float sm[];
    const int tid  = threadIdx.x;
    const int lane = tid & 31;
    const int wid  = tid >> 5;
    const int wm   = wid >> 2;     // 0..3 : 32-row band
    const int wn   = wid & 3;      // 0..3 : 16-col band
    const int gID  = lane >> 2;
    const int tig  = lane & 3;
    const int rowbase = blockIdx.x * MT;

    // cache head weights in smem
    for (int i = tid; i < ADIM * HDIM / 4; i += NT)
        ((float4*)(sm + WPS_OFF))[i] = ((const float4*)wp)[i];
    if (tid < HDIM / 4)
        ((float4*)(sm + WVS_OFF))[tid] = ((const float4*)wv)[tid];

    float* outL  = out;
    float* outV  = out + (size_t)BATCH * ADIM;
    float* hbase = out + (size_t)BATCH * (ADIM + 1);   // [2][B][H]

    // per-thread staging slot geometry (fixed)
    int ar0 = tid >> 3,          aj0 = tid & 7;         // A slot 0: rows 0..63
    int ar1 = (tid + NT) >> 3,   aj1 = (tid + NT) & 7;  // A slot 1: rows 64..127
    int wg[3], wl[3], wj[3];
    #pragma unroll
    for (int i = 0; i < 3; ++i) {
        int u = tid + i * NT;            // 0..1535
        int row = u >> 3;                // 0..191
        wg[i] = row >> 6;                // gate 0..2
        wl[i] = row & 63;                // local col in chunk
        wj[i] = u & 7;
    }

    for (int layer = 0; layer < 2; ++layer) {
        const float* wih = layer ? wih1 : wih0;
        const float* whh = layer ? whh1 : whh0;
        const float* bih = layer ? bih1 : bih0;
        const float* bhh = layer ? bhh1 : bhh0;
        const int    KX  = layer ? HDIM : IDIM;
        const int    ncx = KX >> 5;
        const int    nk  = ncx + (HDIM >> 5);
        const float* asrcx = layer ? (hbase + (size_t)rowbase * HDIM)
                                   : (x + (size_t)rowbase * IDIM);
        const int    axs   = layer ? HDIM : IDIM;
        const float* asrch = hin + (size_t)layer * BATCH * HDIM
                                 + (size_t)rowbase * HDIM;
        float*       hdst  = hbase + (size_t)layer * BATCH * HDIM
                                   + (size_t)rowbase * HDIM;

        // fused biases: [r | z | i_n | h_n] x 256
        #pragma unroll
        for (int it = 0; it < 2; ++it) {
            int i = tid + it * NT;
            int arr = i >> 8, c = i & 255;
            float v;
            if      (arr == 0) v = bih[c]       + bhh[c];
            else if (arr == 1) v = bih[256 + c] + bhh[256 + c];
            else if (arr == 2) v = bih[512 + c];
            else               v = bhh[512 + c];
            sm[BIAS_OFF + i] = v;
        }

        for (int q = 0; q < 4; ++q) {
            const int qc = q * NC;
            float aR[2][2][4], aZ[2][2][4], aI[2][2][4], aH[2][2][4];
            #pragma unroll
            for (int t = 0; t < 2; ++t)
                #pragma unroll
                for (int s = 0; s < 2; ++s)
                    #pragma unroll
                    for (int k = 0; k < 4; ++k) {
                        aR[t][s][k] = 0.f; aZ[t][s][k] = 0.f;
                        aI[t][s][k] = 0.f; aH[t][s][k] = 0.f;
                    }

            // fetch helper (inline): loads 5 float4 for chunk kc
            auto fetch = [&](int kc, float4 v[5]) {
                bool isX = kc < ncx;
                const float* ab  = isX ? asrcx : asrch;
                int          as_ = isX ? axs : HDIM;
                const float* wb  = isX ? wih : whh;
                int          wk  = isX ? KX : HDIM;
                int          ko  = (isX ? kc : kc - ncx) << 5;
                v[0] = *(const float4*)(ab + (size_t)ar0 * as_ + ko + aj0 * 4);
                v[1] = *(const float4*)(ab + (size_t)ar1 * as_ + ko + aj1 * 4);
                #pragma unroll
                for (int i = 0; i < 3; ++i)
                    v[2 + i] = *(const float4*)(wb
                        + (size_t)(wg[i] * 256 + qc + wl[i]) * wk + ko + wj[i] * 4);
            };
            auto store = [&](int buf, const float4 v[5]) {
                float* Ab = sm + buf * BUF_SZ;
                float* Wb = Ab + ASM_SZ;
                *(float4*)&Ab[ar0 * AST + aj0 * 4] = cvt4(v[0]);
                *(float4*)&Ab[ar1 * AST + aj1 * 4] = cvt4(v[1]);
                #pragma unroll
                for (int i = 0; i < 3; ++i)
                    *(float4*)&Wb[(wg[i] * 64 + wl[i]) * AST + wj[i] * 4] =
                        cvt4(v[2 + i]);
            };

            { float4 v0[5]; fetch(0, v0); store(0, v0); }
            __syncthreads();

            for (int kc = 0; kc < nk; ++kc) {
                const bool hn = (kc + 1) < nk;
                float4 v[5];
                if (hn) fetch(kc + 1, v);

                const float* Ab = sm + (kc & 1) * BUF_SZ;
                const float* Wb = Ab + ASM_SZ;
                const bool isX = kc < ncx;

                #pragma unroll
                for (int kk = 0; kk < 4; ++kk) {
                    uint32_t af[2][4];
                    #pragma unroll
                    for (int t = 0; t < 2; ++t) {
                        const float* ap = Ab + (wm * 32 + t * 16 + gID) * AST
                                             + kk * 8 + tig;
                        af[t][0] = __float_as_uint(ap[0]);
                        af[t][1] = __float_as_uint(ap[8 * AST]);
                        af[t][2] = __float_as_uint(ap[4]);
                        af[t][3] = __float_as_uint(ap[8 * AST + 4]);
                    }
                    #pragma unroll
                    for (int s = 0; s < 2; ++s) {
                        const int nr = wn * 16 + s * 8 + gID;
                        const float* w0 = Wb + nr * AST + kk * 8 + tig;
                        uint32_t bR[2], bZ[2], bN[2];
                        bR[0] = __float_as_uint(w0[0]);
                        bR[1] = __float_as_uint(w0[4]);
                        bZ[0] = __float_as_uint(w0[64 * AST]);
                        bZ[1] = __float_as_uint(w0[64 * AST + 4]);
                        bN[0] = __float_as_uint(w0[128 * AST]);
                        bN[1] = __float_as_uint(w0[128 * AST + 4]);
                        #pragma unroll
                        for (int t = 0; t < 2; ++t) {
                            mma8(aR[t][s], af[t], bR);
                            mma8(aZ[t][s], af[t], bZ);
                        }
                        if (isX) {
                            #pragma unroll
                            for (int t = 0; t < 2; ++t) mma8(aI[t][s], af[t], bN);
                        } else {
                            #pragma unroll
                            for (int t = 0; t < 2; ++t) mma8(aH[t][s], af[t], bN);
                        }
                    }
                }
                if (hn) store((kc + 1) & 1, v);
                __syncthreads();
            }

            // elementwise GRU gates from fragments
            #pragma unroll
            for (int t = 0; t < 2; ++t) {
                #pragma unroll
                for (int s = 0; s < 2; ++s) {
                    const int ra = wm * 32 + t * 16 + gID;
                    const int rb = ra + 8;
                    const int c  = qc + wn * 16 + s * 8 + tig * 2;
                    float2 bRv = *(float2*)&sm[BIAS_OFF + c];
                    float2 bZv = *(float2*)&sm[BIAS_OFF + 256 + c];
                    float2 bIv = *(float2*)&sm[BIAS_OFF + 512 + c];
                    float2 bHv = *(float2*)&sm[BIAS_OFF + 768 + c];
                    float2 ha = *(const float2*)&asrch[(size_t)ra * HDIM + c];
                    float2 hb = *(const float2*)&asrch[(size_t)rb * HDIM + c];
                    float2 oa, ob;
                    oa.x = gru1(aR[t][s][0] + bRv.x, aZ[t][s][0] + bZv.x,
                                aI[t][s][0] + bIv.x, aH[t][s][0] + bHv.x, ha.x);
                    oa.y = gru1(aR[t][s][1] + bRv.y, aZ[t][s][1] + bZv.y,
                                aI[t][s][1] + bIv.y, aH[t][s][1] + bHv.y, ha.y);
                    ob.x = gru1(aR[t][s][2] + bRv.x, aZ[t][s][2] + bZv.x,
                                aI[t][s][2] + bIv.x, aH[t][s][2] + bHv.x, hb.x);
                    ob.y = gru1(aR[t][s][3] + bRv.y, aZ[t][s][3] + bZv.y,
                                aI[t][s][3] + bIv.y, aH[t][s][3] + bHv.y, hb.y);
                    *(float2*)&hdst[(size_t)ra * HDIM + c] = oa;
                    *(float2*)&hdst[(size_t)rb * HDIM + c] = ob;
                }
            }
            __syncthreads();
        }
    }

    // heads: logits = h1 @ w_p^T + b_p ; value = h1 @ w_v^T + b_v
    {
        const int row = tid >> 2;
        const int qq  = tid & 3;
        const float* h1r = hbase + (size_t)BATCH * HDIM
                                 + (size_t)(rowbase + row) * HDIM;
        float acc[8];
        #pragma unroll
        for (int a = 0; a < 8; ++a) acc[a] = bp[qq * 8 + a];
        float av = bv[0];
        const float4* h4 = (const float4*)h1r;
        for (int kb = 0; kb < HDIM / 4; ++kb) {
            float4 hv = h4[kb];
            #pragma unroll
            for (int a = 0; a < 8; ++a) {
                const float4 wq =
                    *(const float4*)&sm[WPS_OFF + (qq * 8 + a) * HDIM + kb * 4];
                acc[a] += hv.x * wq.x + hv.y * wq.y + hv.z * wq.z + hv.w * wq.w;
            }
            if (qq == 0) {
                const float4 wq = *(const float4*)&sm[WVS_OFF + kb * 4];
                av += hv.x * wq.x + hv.y * wq.y + hv.z * wq.z + hv.w * wq.w;
            }
        }
        #pragma unroll
        for (int a = 0; a < 8; ++a)
            outL[(size_t)(rowbase + row) * ADIM + qq * 8 + a] = acc[a];
        if (qq == 0) outV[rowbase + row] = av;
    }
}

extern "C" void kernel_launch(void* const* d_in, const int* in_sizes, int n_in,
                              void* d_out, int out_size) {
    const float* x    = (const float*)d_in[0];
    const float* hin  = (const float*)d_in[1];
    const float* wih0 = (const float*)d_in[2];
    const float* whh0 = (const float*)d_in[3];
    const float* bih0 = (const float*)d_in[4];
    const float* bhh0 = (const float*)d_in[5];
    const float* wih1 = (const float*)d_in[6];
    const float* whh1 = (const float*)d_in[7];
    const float* bih1 = (const float*)d_in[8];
    const float* bhh1 = (const float*)d_in[9];
    const float* wp   = (const float*)d_in[10];
    const float* bp   = (const float*)d_in[11];
    const float* wv   = (const float*)d_in[12];
    const float* bv   = (const float*)d_in[13];
    float* out = (float*)d_out;

    cudaFuncSetAttribute(gru_ac_kernel,
                         cudaFuncAttributeMaxDynamicSharedMemorySize, SMEM_DYN);
    gru_ac_kernel<<<NBLK, NT, SMEM_DYN>>>(x, hin, wih0, whh0, bih0, bhh0,
                                          wih1, whh1, bih1, bhh1,
                                          wp, bp, wv, bv, out);
}